// round 9
// baseline (speedup 1.0000x reference)
#include <cuda_runtime.h>
#include <cuda_bf16.h>
#include <math.h>
#include <cstdint>

// Problem constants
constexpr int Bc = 16, Nc = 512, Dc = 512, Hc = 8, DKc = 64;
constexpr int Mrows = Bc * Nc;          // 8192
constexpr int QKV_LD = 3 * Dc;          // 1536
constexpr float SCALE = 0.125f;         // DK^-0.5 (exact power of 2)
constexpr float LN_EPS = 1e-5f;
constexpr int DD = Dc * Dc;

// ---------------------------------------------------------------------------
// Scratch (static device arrays; no allocation allowed)
// ---------------------------------------------------------------------------
__device__ float g_h[Mrows * Dc];
__device__ float g_h2[Mrows * Dc];
__device__ __nv_bfloat16 g_ahi[Mrows * Dc];
__device__ __nv_bfloat16 g_alo[Mrows * Dc];
__device__ __nv_bfloat16 g_qhi[Mrows * Dc];
__device__ __nv_bfloat16 g_qlo[Mrows * Dc];
__device__ __nv_bfloat16 g_khi[Mrows * Dc];
__device__ __nv_bfloat16 g_klo[Mrows * Dc];
__device__ __nv_bfloat16 g_vhi[Mrows * Dc];   // [tok][d] per batch
__device__ __nv_bfloat16 g_vlo[Mrows * Dc];
__device__ __nv_bfloat16 g_vthi[Mrows * Dc];  // [b,h][d][tok]
__device__ __nv_bfloat16 g_vtlo[Mrows * Dc];
__device__ __nv_bfloat16 g_whi[5 * DD];
__device__ __nv_bfloat16 g_wlo[5 * DD];
__device__ float g_bias3[QKV_LD];

// ---------------------------------------------------------------------------
// PTX helpers
// ---------------------------------------------------------------------------
__device__ __forceinline__ uint32_t smem_u32(const void* p) {
    uint32_t a;
    asm("{ .reg .u64 t; cvta.to.shared.u64 t, %1; cvt.u32.u64 %0, t; }" : "=r"(a) : "l"(p));
    return a;
}
__device__ __forceinline__ void ldmx4(uint32_t* r, uint32_t addr) {
    asm volatile("ldmatrix.sync.aligned.m8n8.x4.shared.b16 {%0,%1,%2,%3}, [%4];"
                 : "=r"(r[0]), "=r"(r[1]), "=r"(r[2]), "=r"(r[3]) : "r"(addr));
}
__device__ __forceinline__ void mma16816(float* c, const uint32_t* a, const uint32_t* b) {
    asm volatile("mma.sync.aligned.m16n8k16.row.col.f32.bf16.bf16.f32 "
                 "{%0,%1,%2,%3}, {%4,%5,%6,%7}, {%8,%9}, {%0,%1,%2,%3};"
                 : "+f"(c[0]), "+f"(c[1]), "+f"(c[2]), "+f"(c[3])
                 : "r"(a[0]), "r"(a[1]), "r"(a[2]), "r"(a[3]), "r"(b[0]), "r"(b[1]));
}
__device__ __forceinline__ void cpasync16(uint32_t dst, const void* src) {
    asm volatile("cp.async.cg.shared.global [%0], [%1], 16;" :: "r"(dst), "l"(src));
}
#define CP_COMMIT() asm volatile("cp.async.commit_group;" ::: "memory")
#define CP_WAIT(N)  asm volatile("cp.async.wait_group %0;" :: "n"(N) : "memory")

__device__ __forceinline__ void pack_hilo(float x, float y, uint32_t& hi, uint32_t& lo) {
    __nv_bfloat16 hx = __float2bfloat16(x), hy = __float2bfloat16(y);
    __nv_bfloat16 lx = __float2bfloat16(x - __bfloat162float(hx));
    __nv_bfloat16 ly = __float2bfloat16(y - __bfloat162float(hy));
    __nv_bfloat162 H(hx, hy), L(lx, ly);
    hi = *(uint32_t*)&H;
    lo = *(uint32_t*)&L;
}

// ---------------------------------------------------------------------------
// Weight prep + x split. z<5: weight transpose+split. z>=5: x split slice.
// ---------------------------------------------------------------------------
__global__ void wprep_kernel(const float* __restrict__ W_w, const float* __restrict__ Wq,
                             const float* __restrict__ Wk, const float* __restrict__ Wv,
                             const float* __restrict__ Wo, const float* __restrict__ x,
                             const float* __restrict__ bq, const float* __restrict__ bk,
                             const float* __restrict__ bv,
                             __nv_bfloat16* __restrict__ whi, __nv_bfloat16* __restrict__ wlo,
                             __nv_bfloat16* __restrict__ xhi, __nv_bfloat16* __restrict__ xlo,
                             float* __restrict__ b3)
{
    const int z = blockIdx.z;
    const int tx = threadIdx.x, ty = threadIdx.y;

    if (z >= 5) {
        size_t base = (size_t)(z - 5) * 512 * Dc + (size_t)blockIdx.y * 32 * Dc + blockIdx.x * 32;
        #pragma unroll
        for (int j = 0; j < 32; j += 8) {
            size_t o = base + (size_t)(ty + j) * Dc + tx;
            float v = x[o];
            __nv_bfloat16 h = __float2bfloat16(v);
            xhi[o] = h;
            xlo[o] = __float2bfloat16(v - __bfloat162float(h));
        }
        return;
    }

    __shared__ float t[32][33];
    const float* Ws[5] = {W_w, Wq, Wk, Wv, Wo};
    const float* W = Ws[z];
    __nv_bfloat16* ho = whi + (size_t)z * DD;
    __nv_bfloat16* lop = wlo + (size_t)z * DD;

    const int bx = blockIdx.x * 32;
    const int by = blockIdx.y * 32;

    if (z == 0 && blockIdx.x == 0 && blockIdx.y == 0) {
        int tt = ty * 32 + tx;
        for (int i = tt; i < QKV_LD; i += 256)
            b3[i] = (i < Dc) ? bq[i] : (i < 2 * Dc) ? bk[i - Dc] : bv[i - 2 * Dc];
    }

    #pragma unroll
    for (int j = 0; j < 32; j += 8)
        t[ty + j][tx] = W[(size_t)(by + ty + j) * Dc + bx + tx];
    __syncthreads();
    #pragma unroll
    for (int j = 0; j < 32; j += 8) {
        float v = t[tx][ty + j];
        __nv_bfloat16 h = __float2bfloat16(v);
        size_t o = (size_t)(bx + ty + j) * Dc + by + tx;
        ho[o] = h;
        lop[o] = __float2bfloat16(v - __bfloat162float(h));
    }
}

// ---------------------------------------------------------------------------
// V transpose: [b][tok][h][d] hi/lo -> [b,h][d][tok] hi/lo.
// ---------------------------------------------------------------------------
__global__ void vtprep_kernel(const __nv_bfloat16* __restrict__ vhi,
                              const __nv_bfloat16* __restrict__ vlo,
                              __nv_bfloat16* __restrict__ vthi,
                              __nv_bfloat16* __restrict__ vtlo)
{
    __shared__ __nv_bfloat16 t[64][72];
    const int t0 = blockIdx.x * 64, h = blockIdx.y, b = blockIdx.z;
    const int tid = threadIdx.y * 32 + threadIdx.x;

    const __nv_bfloat16* srcs[2] = {vhi, vlo};
    __nv_bfloat16* dsts[2] = {vthi, vtlo};

    #pragma unroll
    for (int p = 0; p < 2; p++) {
        const __nv_bfloat16* src = srcs[p];
        __nv_bfloat16* dst = dsts[p];
        #pragma unroll
        for (int i = 0; i < 8; i++) {
            int lin = tid + i * 256;
            int tok = lin >> 5, dp = lin & 31;
            uint32_t v = *(const uint32_t*)(src + (size_t)(b * Nc + t0 + tok) * Dc + h * DKc + dp * 2);
            t[tok][dp * 2] = ((__nv_bfloat162*)&v)->x;
            t[tok][dp * 2 + 1] = ((__nv_bfloat162*)&v)->y;
        }
        __syncthreads();
        #pragma unroll
        for (int i = 0; i < 8; i++) {
            int lin = tid + i * 256;
            int d = lin >> 5, tp = lin & 31;
            __nv_bfloat162 o(t[2 * tp][d], t[2 * tp + 1][d]);
            *(uint32_t*)(dst + ((size_t)(b * Hc + h) * DKc + d) * Nc + t0 + 2 * tp) = *(uint32_t*)&o;
        }
        __syncthreads();
    }
}

// ---------------------------------------------------------------------------
// cp.async pipelined mma.sync bf16 split GEMM, single-sync pipeline.
// Pass-major mma order: 16 independent accumulators between reuses.
// MODE 0: fp32 C + bias. MODE 1: relu. MODE 2: qkv epilogue.
// ---------------------------------------------------------------------------
constexpr int GPAD = 40;
constexpr int GTILE_B = 128 * GPAD * 2;   // 10240
constexpr int GSTAGE_B = 4 * GTILE_B;     // 40960
constexpr int GEMM_SMEM = 2 * GSTAGE_B;   // 81920 -> 2 CTAs/SM

template<int MODE>
__global__ void __launch_bounds__(256, 2) mma_gemm_kernel(
    const __nv_bfloat16* __restrict__ Ahi, const __nv_bfloat16* __restrict__ Alo,
    const __nv_bfloat16* __restrict__ Bhi, const __nv_bfloat16* __restrict__ Blo,
    const float* __restrict__ bias, float* __restrict__ C, int ldc,
    __nv_bfloat16* __restrict__ qhi, __nv_bfloat16* __restrict__ qlo,
    __nv_bfloat16* __restrict__ khi, __nv_bfloat16* __restrict__ klo,
    __nv_bfloat16* __restrict__ vhi, __nv_bfloat16* __restrict__ vlo)
{
    extern __shared__ char smem[];
    const uint32_t sbase = smem_u32(smem);
    const int tid = threadIdx.x, wid = tid >> 5, lane = tid & 31;
    const int m0 = blockIdx.y * 128, n0 = blockIdx.x * 128;
    const int wm = wid & 1, wn = wid >> 1;

    const uint32_t aRow = wm * 64 + (lane & 15);
    const uint32_t aCol = (lane < 16) ? 0 : 8;
    const uint32_t aOffB = (aRow * GPAD + aCol) * 2;
    const uint32_t bRow4 = ((lane >> 4) & 1) * 8 + (lane & 7);
    const uint32_t bCol4 = ((lane >> 3) & 1) * 8;

    const int ldRow = tid >> 2, ldSeg = tid & 3;
    const __nv_bfloat16* srcA[4] = {Ahi, Alo, Bhi, Blo};

    auto issue_stage = [&](int c, uint32_t stOff) {
        const int k0 = c * 32;
        #pragma unroll
        for (int t = 0; t < 4; t++) {
            const __nv_bfloat16* src = srcA[t];
            const int base = (t < 2) ? m0 : n0;
            #pragma unroll
            for (int j = 0; j < 2; j++) {
                int row = ldRow + j * 64;
                uint32_t dst = sbase + stOff + t * GTILE_B + (row * GPAD + ldSeg * 8) * 2;
                cpasync16(dst, src + (size_t)(base + row) * Dc + k0 + ldSeg * 8);
            }
        }
        CP_COMMIT();
    };

    float acc[4][4][4] = {};

    constexpr int NCH = Dc / 32;
    issue_stage(0, 0);

    for (int c = 0; c < NCH; c++) {
        const uint32_t stOff = (c & 1) * GSTAGE_B;
        CP_WAIT(0);
        __syncthreads();
        if (c + 1 < NCH) issue_stage(c + 1, (~c & 1) * GSTAGE_B);

        const uint32_t sAhi = sbase + stOff + 0 * GTILE_B;
        const uint32_t sAlo = sbase + stOff + 1 * GTILE_B;
        const uint32_t sBhi = sbase + stOff + 2 * GTILE_B;
        const uint32_t sBlo = sbase + stOff + 3 * GTILE_B;

        #pragma unroll
        for (int ks = 0; ks < 2; ks++) {
            const uint32_t kOffB = ks * 32;
            uint32_t ahi[4][4], alo[4][4], bhi[2][4], blo[2][4];
            #pragma unroll
            for (int i = 0; i < 4; i++) {
                uint32_t ao = aOffB + kOffB + i * 16 * GPAD * 2;
                ldmx4(ahi[i], sAhi + ao);
                ldmx4(alo[i], sAlo + ao);
            }
            #pragma unroll
            for (int jp = 0; jp < 2; jp++) {
                uint32_t bo = ((wn * 32 + jp * 16 + bRow4) * GPAD + bCol4) * 2 + kOffB;
                ldmx4(bhi[jp], sBhi + bo);
                ldmx4(blo[jp], sBlo + bo);
            }
            // pass-major: 16 independent mmas per pass
            #pragma unroll
            for (int i = 0; i < 4; i++)
                #pragma unroll
                for (int j = 0; j < 4; j++)
                    mma16816(acc[i][j], ahi[i], &bhi[j >> 1][(j & 1) * 2]);
            #pragma unroll
            for (int i = 0; i < 4; i++)
                #pragma unroll
                for (int j = 0; j < 4; j++)
                    mma16816(acc[i][j], ahi[i], &blo[j >> 1][(j & 1) * 2]);
            #pragma unroll
            for (int i = 0; i < 4; i++)
                #pragma unroll
                for (int j = 0; j < 4; j++)
                    mma16816(acc[i][j], alo[i], &bhi[j >> 1][(j & 1) * 2]);
        }
    }

    const int lr = lane >> 2, lc = (lane & 3) * 2;
    #pragma unroll
    for (int i = 0; i < 4; i++) {
        const int row0 = m0 + wm * 64 + i * 16 + lr;
        #pragma unroll
        for (int j = 0; j < 4; j++) {
            const int col = n0 + wn * 32 + j * 8 + lc;
            float b0 = bias[col], b1 = bias[col + 1];
            float v0 = acc[i][j][0] + b0, v1 = acc[i][j][1] + b1;
            float v2 = acc[i][j][2] + b0, v3 = acc[i][j][3] + b1;
            if (MODE == 2) {
                uint32_t h0, l0, h1, l1;
                if (n0 < Dc) {            // q: pre-scaled hi/lo
                    size_t o0 = (size_t)row0 * Dc + col;
                    size_t o1 = o0 + 8 * (size_t)Dc;
                    pack_hilo(v0 * SCALE, v1 * SCALE, h0, l0);
                    pack_hilo(v2 * SCALE, v3 * SCALE, h1, l1);
                    *(uint32_t*)(qhi + o0) = h0; *(uint32_t*)(qlo + o0) = l0;
                    *(uint32_t*)(qhi + o1) = h1; *(uint32_t*)(qlo + o1) = l1;
                } else if (n0 < 2 * Dc) { // k: hi/lo
                    size_t o0 = (size_t)row0 * Dc + col - Dc;
                    size_t o1 = o0 + 8 * (size_t)Dc;
                    pack_hilo(v0, v1, h0, l0);
                    pack_hilo(v2, v3, h1, l1);
                    *(uint32_t*)(khi + o0) = h0; *(uint32_t*)(klo + o0) = l0;
                    *(uint32_t*)(khi + o1) = h1; *(uint32_t*)(klo + o1) = l1;
                } else {                  // v: hi/lo (untransposed)
                    size_t o0 = (size_t)row0 * Dc + col - 2 * Dc;
                    size_t o1 = o0 + 8 * (size_t)Dc;
                    pack_hilo(v0, v1, h0, l0);
                    pack_hilo(v2, v3, h1, l1);
                    *(uint32_t*)(vhi + o0) = h0; *(uint32_t*)(vlo + o0) = l0;
                    *(uint32_t*)(vhi + o1) = h1; *(uint32_t*)(vlo + o1) = l1;
                }
            } else {
                if (MODE == 1) {
                    v0 = fmaxf(v0, 0.f); v1 = fmaxf(v1, 0.f);
                    v2 = fmaxf(v2, 0.f); v3 = fmaxf(v3, 0.f);
                }
                *(float2*)(C + (size_t)row0 * ldc + col) = make_float2(v0, v1);
                *(float2*)(C + (size_t)(row0 + 8) * ldc + col) = make_float2(v2, v3);
            }
        }
    }
}

// ---------------------------------------------------------------------------
// LayerNorm over rows of 512, writing bf16 hi/lo split directly.
// ---------------------------------------------------------------------------
__global__ void ln_split_kernel(const float* __restrict__ hsrc,
                                const float* __restrict__ g, const float* __restrict__ b,
                                __nv_bfloat16* __restrict__ hi, __nv_bfloat16* __restrict__ lo)
{
    int warp = (blockIdx.x * blockDim.x + threadIdx.x) >> 5;
    int lane = threadIdx.x & 31;
    if (warp >= Mrows) return;
    const float* row = hsrc + (size_t)warp * Dc;

    float vals[16];
    float s = 0.f;
    #pragma unroll
    for (int i = 0; i < 16; i++) { vals[i] = row[lane + i * 32]; s += vals[i]; }
    #pragma unroll
    for (int o = 16; o > 0; o >>= 1) s += __shfl_xor_sync(0xffffffffu, s, o);
    float mu = s * (1.f / 512.f);

    float vsum = 0.f;
    #pragma unroll
    for (int i = 0; i < 16; i++) { float d = vals[i] - mu; vsum += d * d; }
    #pragma unroll
    for (int o = 16; o > 0; o >>= 1) vsum += __shfl_xor_sync(0xffffffffu, vsum, o);
    float inv = rsqrtf(vsum * (1.f / 512.f) + LN_EPS);

    #pragma unroll
    for (int i = 0; i < 16; i++) {
        int c = lane + i * 32;
        float v = (vals[i] - mu) * inv * g[c] + b[c];
        __nv_bfloat16 h = __float2bfloat16(v);
        hi[(size_t)warp * Dc + c] = h;
        lo[(size_t)warp * Dc + c] = __float2bfloat16(v - __bfloat162float(h));
    }
}

// ---------------------------------------------------------------------------
// mma.sync flash attention; all operands pre-split bf16 in gmem.
// Pass-major S mmas, adj prefetched to a bitmask before the S-loop.
// ---------------------------------------------------------------------------
constexpr int APAD = 72;
constexpr int AQ_B = 128 * APAD * 2;            // 18432 per Q buffer
constexpr int ATILE_B = 64 * APAD * 2;          // 9216 per K/V buffer
constexpr int ASTAGE_B = 4 * ATILE_B;           // 36864
constexpr int ATTN_SMEM = 2 * AQ_B + 2 * ASTAGE_B;   // 110592

__global__ void __launch_bounds__(256, 2) attn_mma_kernel(
    const __nv_bfloat16* __restrict__ qhi, const __nv_bfloat16* __restrict__ qlo,
    const __nv_bfloat16* __restrict__ khi, const __nv_bfloat16* __restrict__ klo,
    const __nv_bfloat16* __restrict__ vthi, const __nv_bfloat16* __restrict__ vtlo,
    const float* __restrict__ adj, const int* __restrict__ use_adj_p,
    __nv_bfloat16* __restrict__ chi, __nv_bfloat16* __restrict__ clo)
{
    extern __shared__ char smemc[];
    const uint32_t sbase = smem_u32(smemc);
    const uint32_t sQhi = sbase, sQlo = sbase + AQ_B;
    const uint32_t sStage = sbase + 2 * AQ_B;

    const int b = blockIdx.z, h = blockIdx.y;
    const int q0 = blockIdx.x * 128;
    const int tid = threadIdx.x, wid = tid >> 5, lane = tid & 31;
    const bool mask = (*use_adj_p) != 0;

    const __nv_bfloat16* vth = vthi + (size_t)(b * Hc + h) * DKc * Nc;
    const __nv_bfloat16* vtl = vtlo + (size_t)(b * Hc + h) * DKc * Nc;

    auto issue_stage = [&](int kt, uint32_t stOff) {
        const int k0 = kt * 64;
        #pragma unroll
        for (int i = 0; i < 2; i++) {
            int ch = tid + i * 256;
            int r = ch >> 3, seg = ch & 7;
            uint32_t so = (r * APAD + seg * 8) * 2;
            size_t gk = (size_t)(b * Nc + k0 + r) * Dc + h * DKc + seg * 8;
            size_t gv = (size_t)r * Nc + k0 + seg * 8;
            cpasync16(stOff + 0 * ATILE_B + so, khi + gk);
            cpasync16(stOff + 1 * ATILE_B + so, klo + gk);
            cpasync16(stOff + 2 * ATILE_B + so, vth + gv);
            cpasync16(stOff + 3 * ATILE_B + so, vtl + gv);
        }
        CP_COMMIT();
    };

    #pragma unroll
    for (int i = 0; i < 4; i++) {
        int ch = tid + i * 256;
        int r = ch >> 3, seg = ch & 7;
        size_t gs = (size_t)(b * Nc + q0 + r) * Dc + h * DKc + seg * 8;
        uint32_t so = (r * APAD + seg * 8) * 2;
        cpasync16(sQhi + so, qhi + gs);
        cpasync16(sQlo + so, qlo + gs);
    }
    issue_stage(0, sStage);

    const uint32_t aRow = wid * 16 + (lane & 15);
    const uint32_t aCol = (lane < 16) ? 0 : 8;
    const uint32_t aOff = (aRow * APAD + aCol) * 2;
    const uint32_t bRow4 = ((lane >> 4) & 1) * 8 + (lane & 7);
    const uint32_t bCol4 = ((lane >> 3) & 1) * 8;

    const int lr = lane >> 2, lc2 = (lane & 3) * 2;
    const int grow0 = q0 + wid * 16 + lr;

    float O[8][4] = {};
    float m0r = -INFINITY, m1r = -INFINITY, l0r = 0.f, l1r = 0.f;

    for (int kt = 0; kt < 8; kt++) {
        const int k0 = kt * 64;
        const uint32_t stOff = sStage + (kt & 1) * ASTAGE_B;
        CP_WAIT(0);
        __syncthreads();
        if (kt + 1 < 8) issue_stage(kt + 1, sStage + (~kt & 1) * ASTAGE_B);

        const uint32_t sKhi = stOff, sKlo = stOff + ATILE_B;
        const uint32_t sVthi = stOff + 2 * ATILE_B, sVtlo = stOff + 3 * ATILE_B;

        // ---- adj bitmask prefetch (LDG latency hides under S mmas) ----
        uint32_t amask = 0xffffffffu;
        if (mask) {
            amask = 0;
            const float* a0 = adj + ((size_t)(b * Nc + grow0)) * Nc + k0 + lc2;
            #pragma unroll
            for (int j = 0; j < 8; j++) {
                float2 x0 = *(const float2*)(a0 + j * 8);
                float2 x1 = *(const float2*)(a0 + 8 * Nc + j * 8);
                uint32_t bits = (x0.x > 0.f ? 1u : 0u) | (x0.y > 0.f ? 2u : 0u)
                              | (x1.x > 0.f ? 4u : 0u) | (x1.y > 0.f ? 8u : 0u);
                amask |= bits << (4 * j);
            }
        }

        // ---- S = Q @ K^T : warp computes [16 x 64], pass-major ----
        float s[8][4];
        #pragma unroll
        for (int j = 0; j < 8; j++)
            #pragma unroll
            for (int u = 0; u < 4; u++) s[j][u] = 0.f;

        #pragma unroll
        for (int ks = 0; ks < 4; ks++) {
            const uint32_t kOff = ks * 32;
            uint32_t ahi[4], alo[4];
            ldmx4(ahi, sQhi + aOff + kOff);
            ldmx4(alo, sQlo + aOff + kOff);
            uint32_t bh[4][4], bl[4][4];
            #pragma unroll
            for (int jp = 0; jp < 4; jp++) {
                uint32_t bo = ((jp * 16 + bRow4) * APAD + bCol4) * 2 + kOff;
                ldmx4(bh[jp], sKhi + bo);
                ldmx4(bl[jp], sKlo + bo);
            }
            // pass 1: ahi * bhi  (8 independent)
            #pragma unroll
            for (int jp = 0; jp < 4; jp++) {
                mma16816(s[2 * jp],     ahi, &bh[jp][0]);
                mma16816(s[2 * jp + 1], ahi, &bh[jp][2]);
            }
            // pass 2: ahi * blo
            #pragma unroll
            for (int jp = 0; jp < 4; jp++) {
                mma16816(s[2 * jp],     ahi, &bl[jp][0]);
                mma16816(s[2 * jp + 1], ahi, &bl[jp][2]);
            }
            // pass 3: alo * bhi
            #pragma unroll
            for (int jp = 0; jp < 4; jp++) {
                mma16816(s[2 * jp],     alo, &bh[jp][0]);
                mma16816(s[2 * jp + 1], alo, &bh[jp][2]);
            }
        }

        // ---- mask apply (bit-test select; Q pre-scaled) ----
        if (mask) {
            #pragma unroll
            for (int j = 0; j < 8; j++) {
                #pragma unroll
                for (int u = 0; u < 4; u++)
                    s[j][u] = (amask >> (4 * j + u)) & 1u ? s[j][u] : 0.f;
            }
        }

        // ---- online softmax ----
        float rm0 = -INFINITY, rm1 = -INFINITY;
        #pragma unroll
        for (int j = 0; j < 8; j++) {
            rm0 = fmaxf(rm0, fmaxf(s[j][0], s[j][1]));
            rm1 = fmaxf(rm1, fmaxf(s[j][2], s[j][3]));
        }
        rm0 = fmaxf(rm0, __shfl_xor_sync(0xffffffffu, rm0, 1));
        rm0 = fmaxf(rm0, __shfl_xor_sync(0xffffffffu, rm0, 2));
        rm1 = fmaxf(rm1, __shfl_xor_sync(0xffffffffu, rm1, 1));
        rm1 = fmaxf(rm1, __shfl_xor_sync(0xffffffffu, rm1, 2));

        float mn0 = fmaxf(m0r, rm0), mn1 = fmaxf(m1r, rm1);
        float al0 = __expf(m0r - mn0), al1 = __expf(m1r - mn1);
        m0r = mn0; m1r = mn1;

        float ps0 = 0.f, ps1 = 0.f;
        #pragma unroll
        for (int j = 0; j < 8; j++) {
            s[j][0] = __expf(s[j][0] - mn0);
            s[j][1] = __expf(s[j][1] - mn0);
            s[j][2] = __expf(s[j][2] - mn1);
            s[j][3] = __expf(s[j][3] - mn1);
            ps0 += s[j][0] + s[j][1];
            ps1 += s[j][2] + s[j][3];
        }
        ps0 += __shfl_xor_sync(0xffffffffu, ps0, 1);
        ps0 += __shfl_xor_sync(0xffffffffu, ps0, 2);
        ps1 += __shfl_xor_sync(0xffffffffu, ps1, 1);
        ps1 += __shfl_xor_sync(0xffffffffu, ps1, 2);
        l0r = l0r * al0 + ps0;
        l1r = l1r * al1 + ps1;

        #pragma unroll
        for (int jd = 0; jd < 8; jd++) {
            O[jd][0] *= al0; O[jd][1] *= al0;
            O[jd][2] *= al1; O[jd][3] *= al1;
        }

        // ---- O += P @ V (alternate-target ordering) ----
        #pragma unroll
        for (int kk = 0; kk < 4; kk++) {
            uint32_t aHi[4], aLo[4];
            pack_hilo(s[2 * kk][0],     s[2 * kk][1],     aHi[0], aLo[0]);
            pack_hilo(s[2 * kk][2],     s[2 * kk][3],     aHi[1], aLo[1]);
            pack_hilo(s[2 * kk + 1][0], s[2 * kk + 1][1], aHi[2], aLo[2]);
            pack_hilo(s[2 * kk + 1][2], s[2 * kk + 1][3], aHi[3], aLo[3]);
            const uint32_t kOff = kk * 32;
            #pragma unroll
            for (int jdp = 0; jdp < 4; jdp++) {
                uint32_t bo = ((jdp * 16 + bRow4) * APAD + bCol4) * 2 + kOff;
                uint32_t bh[4], bl[4];
                ldmx4(bh, sVthi + bo);
                ldmx4(bl, sVtlo + bo);
                mma16816(O[2 * jdp],     aHi, &bh[0]);
                mma16816(O[2 * jdp + 1], aHi, &bh[2]);
                mma16816(O[2 * jdp],     aHi, &bl[0]);
                mma16816(O[2 * jdp + 1], aHi, &bl[2]);
                mma16816(O[2 * jdp],     aLo, &bh[0]);
                mma16816(O[2 * jdp + 1], aLo, &bh[2]);
            }
        }
    }

    const float inv0 = 1.f / l0r, inv1 = 1.f / l1r;
    #pragma unroll
    for (int jd = 0; jd < 8; jd++) {
        size_t o0 = ((size_t)(b * Nc + grow0)) * Dc + h * DKc + jd * 8 + lc2;
        size_t o1 = o0 + 8 * (size_t)Dc;
        uint32_t h0, l0, h1, l1;
        pack_hilo(O[jd][0] * inv0, O[jd][1] * inv0, h0, l0);
        pack_hilo(O[jd][2] * inv1, O[jd][3] * inv1, h1, l1);
        *(uint32_t*)(chi + o0) = h0;
        *(uint32_t*)(clo + o0) = l0;
        *(uint32_t*)(chi + o1) = h1;
        *(uint32_t*)(clo + o1) = l1;
    }
}

// ---------------------------------------------------------------------------
// Gate: coeff = sigmoid([x,h2] . gate_w + gate_b); out = c*x + (1-c)*h2.
// ---------------------------------------------------------------------------
__global__ void gate_kernel(const float* __restrict__ x, const float* __restrict__ h2,
                            const float* __restrict__ gw, const float* __restrict__ gb,
                            float* __restrict__ out)
{
    int warp = (blockIdx.x * blockDim.x + threadIdx.x) >> 5;
    int lane = threadIdx.x & 31;
    if (warp >= Mrows) return;
    const float* xr = x + (size_t)warp * Dc;
    const float* hr = h2 + (size_t)warp * Dc;

    float dot = 0.f;
    #pragma unroll
    for (int i = 0; i < 16; i++) {
        int c = lane + i * 32;
        dot += xr[c] * gw[c] + hr[c] * gw[Dc + c];
    }
    #pragma unroll
    for (int o = 16; o > 0; o >>= 1) dot += __shfl_xor_sync(0xffffffffu, dot, o);

    float z = dot + gb[0];
    float cf = 1.f / (1.f + __expf(-z));
    #pragma unroll
    for (int i = 0; i < 16; i++) {
        int c = lane + i * 32;
        out[(size_t)warp * Dc + c] = cf * xr[c] + (1.f - cf) * hr[c];
    }
}

// ---------------------------------------------------------------------------
extern "C" void kernel_launch(void* const* d_in, const int* in_sizes, int n_in,
                              void* d_out, int out_size)
{
    const float* x    = (const float*)d_in[0];
    const float* adj  = (const float*)d_in[1];
    const float* W_w  = (const float*)d_in[2];
    const float* W_b  = (const float*)d_in[3];
    const float* ln_g = (const float*)d_in[4];
    const float* ln_b = (const float*)d_in[5];
    const float* Wq   = (const float*)d_in[6];
    const float* bq   = (const float*)d_in[7];
    const float* Wk   = (const float*)d_in[8];
    const float* bk   = (const float*)d_in[9];
    const float* Wv   = (const float*)d_in[10];
    const float* bv   = (const float*)d_in[11];
    const float* Wo   = (const float*)d_in[12];
    const float* bo   = (const float*)d_in[13];
    const float* gw   = (const float*)d_in[14];
    const float* gb   = (const float*)d_in[15];
    const int* use_adj = (const int*)d_in[16];
    float* out = (float*)d_out;

    float *h, *h2, *bias3;
    __nv_bfloat16 *ahi, *alo, *whi, *wlo, *qhi, *qlo, *khi, *klo, *vhi, *vlo, *vthi, *vtlo;
    cudaGetSymbolAddress((void**)&h,    g_h);
    cudaGetSymbolAddress((void**)&h2,   g_h2);
    cudaGetSymbolAddress((void**)&ahi,  g_ahi);
    cudaGetSymbolAddress((void**)&alo,  g_alo);
    cudaGetSymbolAddress((void**)&qhi,  g_qhi);
    cudaGetSymbolAddress((void**)&qlo,  g_qlo);
    cudaGetSymbolAddress((void**)&khi,  g_khi);
    cudaGetSymbolAddress((void**)&klo,  g_klo);
    cudaGetSymbolAddress((void**)&vhi,  g_vhi);
    cudaGetSymbolAddress((void**)&vlo,  g_vlo);
    cudaGetSymbolAddress((void**)&vthi, g_vthi);
    cudaGetSymbolAddress((void**)&vtlo, g_vtlo);
    cudaGetSymbolAddress((void**)&whi,  g_whi);
    cudaGetSymbolAddress((void**)&wlo,  g_wlo);
    cudaGetSymbolAddress((void**)&bias3, g_bias3);

    cudaFuncSetAttribute(attn_mma_kernel, cudaFuncAttributeMaxDynamicSharedMemorySize, ATTN_SMEM);
    cudaFuncSetAttribute((const void*)mma_gemm_kernel<0>,
                         cudaFuncAttributeMaxDynamicSharedMemorySize, GEMM_SMEM);
    cudaFuncSetAttribute((const void*)mma_gemm_kernel<1>,
                         cudaFuncAttributeMaxDynamicSharedMemorySize, GEMM_SMEM);
    cudaFuncSetAttribute((const void*)mma_gemm_kernel<2>,
                         cudaFuncAttributeMaxDynamicSharedMemorySize, GEMM_SMEM);

    dim3 wgrid(16, 16, 21), wblk(32, 8);
    dim3 g1(Dc / 128, Mrows / 128);        // (4, 64)
    dim3 gq(QKV_LD / 128, Mrows / 128);    // (12, 64)
    dim3 agrid(Nc / 128, Hc, Bc);          // (4, 8, 16)
    dim3 vgrid(Nc / 64, Hc, Bc);           // (8, 8, 16)

    // 1) weight prep + x split (single kernel)
    wprep_kernel<<<wgrid, wblk>>>(W_w, Wq, Wk, Wv, Wo, x, bq, bk, bv,
                                  whi, wlo, ahi, alo, bias3);
    // 2) h = x @ W_w + W_b
    mma_gemm_kernel<0><<<g1, 256, GEMM_SMEM>>>(ahi, alo, whi, wlo, W_b, h, Dc,
        nullptr, nullptr, nullptr, nullptr, nullptr, nullptr);
    // 3) LN(h) -> hi/lo split
    ln_split_kernel<<<Mrows / 8, 256>>>(h, ln_g, ln_b, ahi, alo);
    // 4) fused QKV GEMM -> q hi/lo (pre-scaled), k hi/lo, v hi/lo
    mma_gemm_kernel<2><<<gq, 256, GEMM_SMEM>>>(ahi, alo, whi + DD, wlo + DD, bias3,
        nullptr, 0, qhi, qlo, khi, klo, vhi, vlo);
    // 5) V transpose per (b,h)
    vtprep_kernel<<<vgrid, wblk>>>(vhi, vlo, vthi, vtlo);
    // 6) mma flash attention -> ctx hi/lo (overwrites ahi/alo)
    attn_mma_kernel<<<agrid, 256, ATTN_SMEM>>>(qhi, qlo, khi, klo, vthi, vtlo,
                                               adj, use_adj, ahi, alo);
    // 7) h2 = relu(ctx @ Wo + bo)
    mma_gemm_kernel<1><<<g1, 256, GEMM_SMEM>>>(ahi, alo, whi + 4 * DD, wlo + 4 * DD, bo, h2, Dc,
        nullptr, nullptr, nullptr, nullptr, nullptr, nullptr);
    // 8) gated residual output
    gate_kernel<<<Mrows / 8, 256>>>(x, h2, gw, gb, out);
}